// round 10
// baseline (speedup 1.0000x reference)
#include <cuda_runtime.h>
#include <math.h>
#include <stdint.h>

// Problem shape (fixed by setup_inputs)
#define BATCH 256
#define TLEN  1024
#define DDIM  256
#define LOG2PI 1.8378770664093453f

// Main-kernel tiling
#define GBTOT   8                 // batches per block
#define NCHUNK  64                // t-chunks
#define CHUNK   (TLEN / NCHUNK)   // 16
#define BSTRIDE (TLEN * DDIM)     // elements between batches (1MB)

// Table: 3 SoA sections; row 0 encodes the initial term (A=0, R=1/sqrt(var0),
// C=-mu/sqrt(var0)), rows t>=1 the transitions.
#define SEC    (TLEN * DDIM)
#define SEC_A  0
#define SEC_R  SEC
#define SEC_C  (2 * SEC)
__device__ float g_tabf[3 * SEC];
__device__ float g_row[TLEN];       // per-t row sums of log q + LOG2PI

// Dynamic smem layout for k_main
#define ROWB    (DDIM * 4)          // 1024 B per t-row
#define BUFROWS (CHUNK + 1)         // 17 (includes prev row)
#define BUFB    (BUFROWS * ROWB)    // 17408 B
#define NBUF    4
#define MBAR_OFF (NBUF * BUFB)      // 69632
#define RED_OFF  (MBAR_OFF + 64)
#define SMEMB    (RED_OFF + 2 * 8 * 4)   // 69760 B

__device__ __forceinline__ float softplusf(float x) {
    return (x > 20.f) ? x : log1pf(expf(x));
}

__device__ __forceinline__ uint32_t smem_u32(const void* p) {
    uint32_t a;
    asm("{ .reg .u64 t; cvta.to.shared.u64 t, %1; cvt.u32.u64 %0, t; }"
        : "=r"(a) : "l"(p));
    return a;
}
__device__ __forceinline__ void mbar_init(uint32_t mbar, uint32_t count) {
    asm volatile("mbarrier.init.shared.b64 [%0], %1;" :: "r"(mbar), "r"(count) : "memory");
}
__device__ __forceinline__ void mbar_expect_tx(uint32_t mbar, uint32_t bytes) {
    asm volatile("mbarrier.arrive.expect_tx.shared.b64 _, [%0], %1;"
                 :: "r"(mbar), "r"(bytes) : "memory");
}
__device__ __forceinline__ void bulk_g2s(uint32_t dst, const void* src,
                                         uint32_t bytes, uint32_t mbar) {
    asm volatile("cp.async.bulk.shared::cluster.global.mbarrier::complete_tx::bytes "
                 "[%0], [%1], %2, [%3];"
                 :: "r"(dst), "l"(src), "r"(bytes), "r"(mbar) : "memory");
}
__device__ __forceinline__ void mbar_wait(uint32_t mbar, uint32_t parity) {
    uint32_t done = 0;
    while (!done) {
        asm volatile("{\n\t.reg .pred p;\n\t"
                     "mbarrier.try_wait.parity.acquire.cta.shared::cta.b64 p, [%1], %2;\n\t"
                     "selp.b32 %0, 1, 0, p;\n\t}"
                     : "=r"(done) : "r"(mbar), "r"(parity) : "memory");
    }
}

// ---------------------------------------------------------------------------
// Kernel 1: precompute table + per-row log constants; zero the output.
// grid = TLEN blocks, block = DDIM threads
// ---------------------------------------------------------------------------
__global__ void k_precompute(const float* __restrict__ ts,
                             const float* __restrict__ log_kappa,
                             const float* __restrict__ log_sigma,
                             const float* __restrict__ mu,
                             float* __restrict__ out, int out_size) {
    const int t = blockIdx.x;
    const int d = threadIdx.x;

    float kappa = softplusf(log_kappa[d]) + 1e-6f;
    float sigma = softplusf(log_sigma[d]) + 1e-6f;
    float s2 = sigma * sigma;
    float mu_d = mu[d];

    float elem;
    const int idx = t * DDIM + d;
    if (t == 0) {
        float var0 = fmaxf(s2 / (2.0f * kappa), 1e-10f);
        float r0 = rsqrtf(var0);
        g_tabf[SEC_A + idx] = 0.0f;
        g_tabf[SEC_R + idx] = r0;
        g_tabf[SEC_C + idx] = -mu_d * r0;
        elem = logf(var0) + LOG2PI;
        for (int i = d; i < out_size; i += blockDim.x) out[i] = 0.0f;
    } else {
        float dt = fmaxf(ts[t * DDIM + d] - ts[(t - 1) * DDIM + d], 1e-6f);
        float Ad = expf(-kappa * dt);
        float q  = fmaxf(s2 * (-expm1f(-2.0f * kappa * dt)) / (2.0f * kappa), 1e-10f);
        float R  = rsqrtf(q);
        g_tabf[SEC_A + idx] = Ad;
        g_tabf[SEC_R + idx] = R;
        g_tabf[SEC_C + idx] = -mu_d * (1.0f - Ad) * R;
        elem = logf(q) + LOG2PI;
    }

    __shared__ float sm[DDIM];
    sm[d] = elem;
    __syncthreads();
    for (int s = DDIM / 2; s > 0; s >>= 1) {
        if (d < s) sm[d] += sm[d + s];
        __syncthreads();
    }
    if (d == 0) g_row[t] = sm[0];
}

// ---------------------------------------------------------------------------
// Kernel 2: bulk-copy staged streaming pass.
// grid = 2048 blocks (32 batch-groups x 64 chunks), 256 threads.
// Per block: 8 batches; y staged via cp.async.bulk as 17KB contiguous slices
// into 4 smem buffers (4 mbarriers). Batches processed in pairs: warps 0-3
// (hh=0) handle batch 2k, warps 4-7 (hh=1) handle batch 2k+1; thread owns a
// d-pair. Table is L1-cached LDG.64. Each block folds in its chunk's share
// of the log-det constant.
// ---------------------------------------------------------------------------
__global__ __launch_bounds__(256, 3)
void k_main(const float* __restrict__ y, float* __restrict__ out) {
    extern __shared__ __align__(16) unsigned char smraw[];

    const int c     = blockIdx.x & (NCHUNK - 1);
    const int bbase = (blockIdx.x >> 6) * GBTOT;
    const int tid   = threadIdx.x;
    const int p     = tid & 127;        // d-pair: d = {2p, 2p+1}
    const int hh    = tid >> 7;         // half: batch 2k+hh
    const int lane  = tid & 31;
    const int warp  = tid >> 5;

    const int tstart = c * CHUNK;
    const int start  = (c == 0) ? 0 : (tstart - 1);   // first staged row
    const int ibase  = (c == 0) ? 0 : 1;              // smem row of t=tstart

    const uint32_t mbar0 = smem_u32(smraw + MBAR_OFF);
    float* red = (float*)(smraw + RED_OFF);           // [2][8]

    // init barriers + prologue copies (batches 0..3 -> bufs 0..3)
    if (tid == 0) {
#pragma unroll
        for (int i = 0; i < NBUF; i++) mbar_init(mbar0 + 8 * i, 1);
    }
    __syncthreads();
    if (tid == 0) {
#pragma unroll
        for (int i = 0; i < NBUF; i++) {
            mbar_expect_tx(mbar0 + 8 * i, BUFB);
            bulk_g2s(smem_u32(smraw + i * BUFB),
                     y + (size_t)(bbase + i) * BSTRIDE + (size_t)start * DDIM,
                     BUFB, mbar0 + 8 * i);
        }
    }

    // chunk constant (thread 0 keeps it)
    float chunkC = 0.0f;
    if (warp == 0) {
        float v = (lane < CHUNK) ? __ldg(&g_row[tstart + lane]) : 0.0f;
#pragma unroll
        for (int o = 16; o > 0; o >>= 1) v += __shfl_down_sync(0xffffffffu, v, o);
        chunkC = v;   // valid in lane 0
    }

    const float* __restrict__ tb = g_tabf + (size_t)tstart * DDIM + 2 * p;

#pragma unroll
    for (int k = 0; k < GBTOT / 2; k++) {
        const int s = (2 * k + hh) & 3;               // my buffer
        mbar_wait(mbar0 + 8 * s, (k >> 1) & 1);

        const float* buf = (const float*)(smraw + s * BUFB) + 2 * p;
        float2 prev = *(const float2*)(buf);          // row 0 (prev row / A=0)
        float accv = 0.0f;
#pragma unroll
        for (int j = 0; j < CHUNK; j++) {
            float2 cur = *(const float2*)(buf + (ibase + j) * DDIM);
            const float* tt = tb + j * DDIM;
            float2 A  = __ldg((const float2*)(tt + SEC_A));
            float2 R  = __ldg((const float2*)(tt + SEC_R));
            float2 Cc = __ldg((const float2*)(tt + SEC_C));
            float x0 = fmaf(-A.x, prev.x, cur.x);
            float x1 = fmaf(-A.y, prev.y, cur.y);
            float z0 = fmaf(x0, R.x, Cc.x);
            float z1 = fmaf(x1, R.y, Cc.y);
            accv = fmaf(z0, z0, accv);
            accv = fmaf(z1, z1, accv);
            prev = cur;
        }

        // warp reduce, stash per-warp partial (double-buffered by k&1)
#pragma unroll
        for (int o = 16; o > 0; o >>= 1)
            accv += __shfl_down_sync(0xffffffffu, accv, o);
        if (lane == 0) red[(k & 1) * 8 + warp] = accv;
        __syncthreads();

        if (tid == 0) {
            float* r = red + (k & 1) * 8;
            float s0 = r[0] + r[1] + r[2] + r[3];
            float s1 = r[4] + r[5] + r[6] + r[7];
            atomicAdd(&out[bbase + 2 * k + 0], -0.5f * (s0 + chunkC));
            atomicAdd(&out[bbase + 2 * k + 1], -0.5f * (s1 + chunkC));
            if (k < 2) {   // refill both buffers of this pair with batches +4
#pragma unroll
                for (int i = 0; i < 2; i++) {
                    int g = 2 * k + 4 + i;
                    int sb = g & 3;
                    mbar_expect_tx(mbar0 + 8 * sb, BUFB);
                    bulk_g2s(smem_u32(smraw + sb * BUFB),
                             y + (size_t)(bbase + g) * BSTRIDE + (size_t)start * DDIM,
                             BUFB, mbar0 + 8 * sb);
                }
            }
        }
    }
}

extern "C" void kernel_launch(void* const* d_in, const int* in_sizes, int n_in,
                              void* d_out, int out_size) {
    const float* y  = (const float*)d_in[0];
    const float* ts = (const float*)d_in[1];
    const float* mu = (const float*)d_in[2];
    const float* lk = (const float*)d_in[3];
    const float* ls = (const float*)d_in[4];
    float* out = (float*)d_out;

    // Opt in to >48KB dynamic smem (idempotent; ignore error under capture).
    static int attr_done = 0;
    if (!attr_done) {
        cudaFuncSetAttribute(k_main, cudaFuncAttributeMaxDynamicSharedMemorySize, SMEMB);
        attr_done = 1;
    }

    k_precompute<<<TLEN, DDIM>>>(ts, lk, ls, mu, out, out_size);
    k_main<<<(BATCH / GBTOT) * NCHUNK, 256, SMEMB>>>(y, out);
}

// round 11
// speedup vs baseline: 1.0920x; 1.0920x over previous
#include <cuda_runtime.h>
#include <math.h>

// Problem shape (fixed by setup_inputs)
#define BATCH 256
#define TLEN  1024
#define DDIM  256
#define LOG2PI 1.8378770664093453f

// Tiling
#define GBTOT   8                 // batches per block (2 halves x 4)
#define GBH     4                 // batches per thread half
#define NCHUNK  32                // t-chunks per batch-group
#define CHUNK   (TLEN / NCHUNK)   // 32
#define NGROUP  (BATCH / GBTOT)   // 32
#define BSTRIDE (TLEN * DDIM)     // elements between batches (1MB)

// Persistent scratch (plain-store overwritten each launch; counter monotonic)
__device__ float        g_part[NGROUP][NCHUNK][GBTOT];
__device__ unsigned int g_cnt[NGROUP];   // zero-initialized at module load

__device__ __forceinline__ float softplusf(float x) {
    return (x > 20.f) ? x : log1pf(expf(x));
}

// ---------------------------------------------------------------------------
// Single fused kernel. grid = 1024 blocks (32 groups x 32 chunks), 256 thr.
// dv = tid&127 owns d = {2dv, 2dv+1}; h = tid>>7 handles 4 batches.
// OU coefficients computed on the fly from ts (L2-hot):
//   A = exp(-kappa dt), q = var_inf (1 - A^2), R = 1/sqrt(q),
//   C = mu (A-1) R, z = fma(fma(-A,prev,y), R, C), acc += z^2
//   log q = -2 log R  (accumulated by half 0 only -> chunk constant)
// t=0 folds in exactly: var0 = sigma^2/(2 kappa) = var_inf, A = 0.
// Output: per-chunk partials -> g_part (plain STG), persistent-counter
// election sums 32 partials per group in fixed order and writes out once.
// ---------------------------------------------------------------------------
__global__ __launch_bounds__(256, 3)
void k_fused(const float* __restrict__ y,  const float* __restrict__ ts,
             const float* __restrict__ mu, const float* __restrict__ lk,
             const float* __restrict__ ls, float* __restrict__ out) {
    const int c     = blockIdx.x & (NCHUNK - 1);
    const int grp   = blockIdx.x >> 5;
    const int bbase = grp * GBTOT;
    const int tid   = threadIdx.x;
    const int dv    = tid & 127;
    const int h     = tid >> 7;
    const int lane  = tid & 31;
    const int warp  = tid >> 5;

    // per-d parameters (2 d's per thread)
    const int d0 = 2 * dv;
    const float2 mu2 = *(const float2*)(mu + d0);
    const float2 lk2 = *(const float2*)(lk + d0);
    const float2 ls2 = *(const float2*)(ls + d0);
    const float kx = softplusf(lk2.x) + 1e-6f;
    const float ky = softplusf(lk2.y) + 1e-6f;
    const float spx = softplusf(ls2.x) + 1e-6f;
    const float spy = softplusf(ls2.y) + 1e-6f;
    const float vix = spx * spx / (2.0f * kx);   // var_inf = var0
    const float viy = spy * spy / (2.0f * ky);

    const int tstart = c * CHUNK;
    const int prow   = (c == 0) ? 0 : (tstart - 1);  // prev row (unused val at c==0)

    const float* __restrict__ yb  = y  + (size_t)(bbase + h * GBH) * BSTRIDE + d0;
    const float* __restrict__ tsb = ts + d0;

    float2 prev[GBH];
    float  acc[GBH];
#pragma unroll
    for (int g = 0; g < GBH; g++) {
        prev[g] = __ldcs((const float2*)(yb + (size_t)prow * DDIM + g * BSTRIDE));
        acc[g]  = 0.0f;
    }
    float2 tsp = *(const float2*)(tsb + (size_t)prow * DDIM);
    float logsum = (h == 0) ? (2.0f * CHUNK * LOG2PI) : 0.0f;

    const float* __restrict__ yt  = yb  + (size_t)tstart * DDIM;
    const float* __restrict__ tst = tsb + (size_t)tstart * DDIM;

#pragma unroll 4
    for (int i = 0; i < CHUNK / 2; i++) {
        // front-batched loads: 8 y LDG.64 (DRAM) + 2 ts LDG.64 (L2-hot)
        float2 yv[2][GBH];
#pragma unroll
        for (int u = 0; u < 2; u++)
#pragma unroll
            for (int g = 0; g < GBH; g++)
                yv[u][g] = __ldcs((const float2*)(yt + (2 * i + u) * DDIM
                                                  + g * BSTRIDE));
        float2 tw[2];
#pragma unroll
        for (int u = 0; u < 2; u++)
            tw[u] = __ldg((const float2*)(tst + (2 * i + u) * DDIM));

#pragma unroll
        for (int u = 0; u < 2; u++) {
            float dtx = fmaxf(tw[u].x - tsp.x, 1e-6f);
            float dty = fmaxf(tw[u].y - tsp.y, 1e-6f);
            float Ax = __expf(-kx * dtx);
            float Ay = __expf(-ky * dty);
            float qx = fmaxf(vix * (1.0f - Ax * Ax), 1e-10f);
            float qy = fmaxf(viy * (1.0f - Ay * Ay), 1e-10f);
            if (i == 0 && u == 0 && c == 0) {       // initial term: A=0, q=var0
                Ax = 0.0f; Ay = 0.0f;
                qx = fmaxf(vix, 1e-10f);
                qy = fmaxf(viy, 1e-10f);
            }
            float Rx = rsqrtf(qx), Ry = rsqrtf(qy);
            float Cx = (Ax - 1.0f) * Rx * mu2.x;    // = -mu (1-A) R
            float Cy = (Ay - 1.0f) * Ry * mu2.y;
            if (h == 0)                              // log q = -2 log R
                logsum -= 2.0f * (__logf(Rx) + __logf(Ry));
#pragma unroll
            for (int g = 0; g < GBH; g++) {
                float xx = fmaf(-Ax, prev[g].x, yv[u][g].x);
                float xy = fmaf(-Ay, prev[g].y, yv[u][g].y);
                float zx = fmaf(xx, Rx, Cx);
                float zy = fmaf(xy, Ry, Cy);
                acc[g] = fmaf(zx, zx, acc[g]);
                acc[g] = fmaf(zy, zy, acc[g]);
                prev[g] = yv[u][g];
            }
            tsp = tw[u];
        }
    }

    // ---- block reduce: residuals per batch + chunk log-constant ----
    __shared__ float sm[8][GBH];
    __shared__ float sml[4];
#pragma unroll
    for (int g = 0; g < GBH; g++) {
        float v = acc[g];
#pragma unroll
        for (int o = 16; o > 0; o >>= 1) v += __shfl_down_sync(0xffffffffu, v, o);
        if (lane == 0) sm[warp][g] = v;
    }
    {
        float v = logsum;
#pragma unroll
        for (int o = 16; o > 0; o >>= 1) v += __shfl_down_sync(0xffffffffu, v, o);
        if (h == 0 && lane == 0) sml[warp] = v;
    }
    __syncthreads();

    if (tid < GBTOT) {
        int q2 = tid >> 2, g = tid & 3;             // batch = q2*4+g = tid
        float chunkC = sml[0] + sml[1] + sml[2] + sml[3];
        float s = sm[q2 * 4 + 0][g] + sm[q2 * 4 + 1][g]
                + sm[q2 * 4 + 2][g] + sm[q2 * 4 + 3][g];
        g_part[grp][c][tid] = s + chunkC;
    }
    __threadfence();
    __syncthreads();

    // ---- persistent-counter election: last chunk-block of the group sums ----
    __shared__ unsigned int slast;
    if (tid == 0) {
        unsigned int old = atomicAdd(&g_cnt[grp], 1u);
        slast = (((old + 1) & (NCHUNK - 1)) == 0) ? 1u : 0u;
    }
    __syncthreads();
    if (slast) {
        __threadfence();
        if (tid < GBTOT) {
            float tot = 0.0f;
#pragma unroll
            for (int ch = 0; ch < NCHUNK; ch++)
                tot += __ldcg(&g_part[grp][ch][tid]);
            out[bbase + tid] = -0.5f * tot;
        }
    }
}

extern "C" void kernel_launch(void* const* d_in, const int* in_sizes, int n_in,
                              void* d_out, int out_size) {
    const float* y  = (const float*)d_in[0];
    const float* ts = (const float*)d_in[1];
    const float* mu = (const float*)d_in[2];
    const float* lk = (const float*)d_in[3];
    const float* ls = (const float*)d_in[4];
    float* out = (float*)d_out;

    k_fused<<<NGROUP * NCHUNK, 256>>>(y, ts, mu, lk, ls, out);
}

// round 12
// speedup vs baseline: 1.2714x; 1.1643x over previous
#include <cuda_runtime.h>
#include <math.h>

// Problem shape (fixed by setup_inputs)
#define BATCH 256
#define TLEN  1024
#define DDIM  256
#define LOG2PI 1.8378770664093453f

// Main-kernel tiling (R5 proven-best configuration)
#define GBTOT   8                 // batches per block (2 halves x 4)
#define GBH     4                 // batches per thread half
#define NCHUNK  32                // t-chunks
#define CHUNK   (TLEN / NCHUNK)   // 32
#define BSTRIDE (TLEN * DDIM)     // elements between batches (1MB)

// Precompute tiling
#define PROWS   2                 // t-rows per precompute block

// Table: 3 SoA sections of (TLEN-1)*DDIM floats each, one base pointer so
// section offsets fold into LDG immediates.
#define SEC    ((TLEN - 1) * DDIM)
#define SEC_A  0
#define SEC_R  SEC
#define SEC_C  (2 * SEC)
__device__ float g_tabf[3 * SEC];   // A=exp(-k dt), R=1/sqrt(q), C=-mu*(1-A)*R
__device__ float g_r0[DDIM];        // 1/sqrt(var0)
__device__ float g_c0[DDIM];        // -mu/sqrt(var0)
__device__ float g_row[TLEN];       // per-t row sums of log q + LOG2PI

__device__ __forceinline__ float softplusf(float x) {
    return (x > 20.f) ? x : log1pf(expf(x));
}

// ---------------------------------------------------------------------------
// Kernel 1: precompute table + per-row log constants; zero the output.
// grid = TLEN/PROWS blocks, block = DDIM threads; each block handles PROWS
// consecutive t-rows, amortizing the softplus/parameter chain across rows.
// ---------------------------------------------------------------------------
__global__ void k_precompute(const float* __restrict__ ts,
                             const float* __restrict__ log_kappa,
                             const float* __restrict__ log_sigma,
                             const float* __restrict__ mu,
                             float* __restrict__ out, int out_size) {
    const int tbase = blockIdx.x * PROWS;
    const int d = threadIdx.x;

    const float kappa = softplusf(log_kappa[d]) + 1e-6f;
    const float sigma = softplusf(log_sigma[d]) + 1e-6f;
    const float s2 = sigma * sigma;
    const float mu_d = mu[d];
    const float inv2k = 1.0f / (2.0f * kappa);

    __shared__ float sm[PROWS][DDIM];

    float tprev = (tbase > 0) ? ts[(tbase - 1) * DDIM + d] : 0.0f;

#pragma unroll
    for (int r = 0; r < PROWS; r++) {
        const int t = tbase + r;
        float elem;
        if (t == 0) {
            float var0 = fmaxf(s2 * inv2k, 1e-10f);
            float r0 = rsqrtf(var0);
            g_r0[d] = r0;
            g_c0[d] = -mu_d * r0;
            elem = logf(var0) + LOG2PI;
            for (int i = d; i < out_size; i += blockDim.x) out[i] = 0.0f;
            tprev = ts[d];   // prepare for t=1 (row 0 of ts)
        } else {
            float tcur = ts[t * DDIM + d];
            float dt = fmaxf(tcur - tprev, 1e-6f);
            float Ad = expf(-kappa * dt);
            float q  = fmaxf(s2 * (-expm1f(-2.0f * kappa * dt)) * inv2k, 1e-10f);
            float R  = rsqrtf(q);
            int idx = (t - 1) * DDIM + d;
            g_tabf[SEC_A + idx] = Ad;
            g_tabf[SEC_R + idx] = R;
            g_tabf[SEC_C + idx] = -mu_d * (1.0f - Ad) * R;
            elem = logf(q) + LOG2PI;
            tprev = tcur;
        }
        sm[r][d] = elem;
    }
    __syncthreads();
    // reduce each of the PROWS rows (256 -> 1)
    for (int s = DDIM / 2; s > 0; s >>= 1) {
        if (d < s) {
#pragma unroll
            for (int r = 0; r < PROWS; r++) sm[r][d] += sm[r][d + s];
        }
        __syncthreads();
    }
    if (d < PROWS) g_row[tbase + d] = sm[d][0];
}

// ---------------------------------------------------------------------------
// Kernel 2: main streaming pass (R5 configuration, proven 48.4us).
// grid = 1024 blocks, block = 256 threads.
// dv = tid&127 covers d = {2dv, 2dv+1}; h = tid>>7 handles 4 batches.
// 4-deep t-window: all 16 y LDG.64 front-batched (covers DRAM latency);
// table loads just-in-time (L1/L2 hits). z = fma(fma(-A,prev,y), R, C).
// ---------------------------------------------------------------------------
__global__ __launch_bounds__(256, 4)
void k_main(const float* __restrict__ y, float* __restrict__ out) {
    const int c     = blockIdx.x & (NCHUNK - 1);
    const int bbase = (blockIdx.x >> 5) * GBTOT;
    const int tid   = threadIdx.x;
    const int dv    = tid & 127;
    const int h     = tid >> 7;

    const float* __restrict__ yb =
        y + (size_t)(bbase + h * GBH) * BSTRIDE + 2 * dv;

    const int tstart = c * CHUNK;
    const int t0   = (c == 0) ? 1 : tstart;
    const int tend = tstart + CHUNK;

    float2 prev[GBH];
    float  acc[GBH];
#pragma unroll
    for (int g = 0; g < GBH; g++)
        prev[g] = *(const float2*)(yb + (size_t)(t0 - 1) * DDIM + g * BSTRIDE);

    if (c == 0) {
        float2 r0 = *(const float2*)(g_r0 + 2 * dv);
        float2 c0 = *(const float2*)(g_c0 + 2 * dv);
#pragma unroll
        for (int g = 0; g < GBH; g++) {
            float zx = fmaf(prev[g].x, r0.x, c0.x);
            float zy = fmaf(prev[g].y, r0.y, c0.y);
            acc[g] = zx * zx + zy * zy;
        }
    } else {
#pragma unroll
        for (int g = 0; g < GBH; g++) acc[g] = 0.0f;
    }

    const float* __restrict__ tb = g_tabf + 2 * dv;

    int t = t0;
    for (; t + 3 < tend; t += 4) {
        // ---- front-batched y loads: 16 LDG.64 back-to-back (DRAM MLP) ----
        float2 yv[4][GBH];
        const float* yt = yb + (size_t)t * DDIM;
#pragma unroll
        for (int u = 0; u < 4; u++)
#pragma unroll
            for (int g = 0; g < GBH; g++)
                yv[u][g] = __ldcs((const float2*)(yt + u * DDIM + g * BSTRIDE));

        // ---- per-step table loads (L1/L2 hits) + compute ----
        const float* tt = tb + (size_t)(t - 1) * DDIM;
#pragma unroll
        for (int u = 0; u < 4; u++) {
            float2 A  = __ldg((const float2*)(tt + u * DDIM + SEC_A));
            float2 R  = __ldg((const float2*)(tt + u * DDIM + SEC_R));
            float2 Cc = __ldg((const float2*)(tt + u * DDIM + SEC_C));
#pragma unroll
            for (int g = 0; g < GBH; g++) {
                float xx = fmaf(-A.x, prev[g].x, yv[u][g].x);
                float xy = fmaf(-A.y, prev[g].y, yv[u][g].y);
                float zx = fmaf(xx, R.x, Cc.x);
                float zy = fmaf(xy, R.y, Cc.y);
                acc[g] = fmaf(zx, zx, acc[g]);
                acc[g] = fmaf(zy, zy, acc[g]);
                prev[g] = yv[u][g];
            }
        }
    }
    // remainder (only for c==0: 3 iterations)
    for (; t < tend; ++t) {
        const float* tt = tb + (size_t)(t - 1) * DDIM;
        float2 A  = __ldg((const float2*)(tt + SEC_A));
        float2 R  = __ldg((const float2*)(tt + SEC_R));
        float2 Cc = __ldg((const float2*)(tt + SEC_C));
#pragma unroll
        for (int g = 0; g < GBH; g++) {
            float2 yv = __ldcs((const float2*)(yb + (size_t)t * DDIM + g * BSTRIDE));
            float xx = fmaf(-A.x, prev[g].x, yv.x);
            float xy = fmaf(-A.y, prev[g].y, yv.y);
            float zx = fmaf(xx, R.x, Cc.x);
            float zy = fmaf(xy, R.y, Cc.y);
            acc[g] = fmaf(zx, zx, acc[g]);
            acc[g] = fmaf(zy, zy, acc[g]);
            prev[g] = yv;
        }
    }

    // ---- reduce: warp shuffle per g, cross-warp via smem ----
    const int lane = tid & 31;
    const int warp = tid >> 5;
    __shared__ float sm[8][GBH];
#pragma unroll
    for (int g = 0; g < GBH; g++) {
        float v = acc[g];
#pragma unroll
        for (int o = 16; o > 0; o >>= 1) v += __shfl_down_sync(0xffffffffu, v, o);
        if (lane == 0) sm[warp][g] = v;
    }
    __syncthreads();

    // chunk constant: sum of this chunk's 32 g_row entries (warp 0)
    float chunkC = 0.0f;
    if (warp == 0) {
        float v = g_row[tstart + lane];
#pragma unroll
        for (int o = 16; o > 0; o >>= 1) v += __shfl_down_sync(0xffffffffu, v, o);
        chunkC = __shfl_sync(0xffffffffu, v, 0);
    }

    if (tid < GBTOT) {
        int h2 = tid >> 2;
        int g  = tid & 3;
        float s = sm[h2 * 4 + 0][g] + sm[h2 * 4 + 1][g]
                + sm[h2 * 4 + 2][g] + sm[h2 * 4 + 3][g];
        atomicAdd(&out[bbase + h2 * GBH + g], -0.5f * (s + chunkC));
    }
}

extern "C" void kernel_launch(void* const* d_in, const int* in_sizes, int n_in,
                              void* d_out, int out_size) {
    const float* y  = (const float*)d_in[0];
    const float* ts = (const float*)d_in[1];
    const float* mu = (const float*)d_in[2];
    const float* lk = (const float*)d_in[3];
    const float* ls = (const float*)d_in[4];
    float* out = (float*)d_out;

    k_precompute<<<TLEN / PROWS, DDIM>>>(ts, lk, ls, mu, out, out_size);
    k_main<<<(BATCH / GBTOT) * NCHUNK, 256>>>(y, out);
}